// round 1
// baseline (speedup 1.0000x reference)
#include <cuda_runtime.h>
#include <math.h>
#include <stdint.h>

#define BB 8
#define NN 4096
#define FF 64
#define OO 64
#define KK 20
#define NPTS (BB*NN)
#define FULLM 0xFFFFFFFFu

// ---------------- scratch (device globals: no allocation allowed) ----------------
__device__ float  g_sq[NPTS];
__device__ float  g_u[NPTS*OO];
__device__ float  g_v[NPTS*OO];
__device__ int    g_idx[NPTS*KK];
__device__ float  g_hmax[NPTS*OO];
__device__ float  g_hmin[NPTS*OO];
__device__ double g_sum[OO];
__device__ double g_ssq[OO];
__device__ float  g_scale[OO];
__device__ float  g_shift[OO];

// ---------------- zero the stat accumulators (graph replays reuse globals) -------
__global__ void k_zero() {
    int t = threadIdx.x;
    if (t < OO) { g_sum[t] = 0.0; g_ssq[t] = 0.0; }
}

// ---------------- u = x*(W1-W2)^T, v = x*W2^T, plus squared norms ----------------
// block: 256 thr = 8 warps; each warp handles 8 points. W staged in smem [f][o].
__global__ __launch_bounds__(256) void k_uv(const float* __restrict__ x,
                                            const float* __restrict__ W) {
    __shared__ float Wm[FF*OO];   // (W1 - W2)[f][o]
    __shared__ float W2s[FF*OO];  // W2[f][o]
    __shared__ float xbuf[8][FF];

    for (int i = threadIdx.x; i < FF*OO; i += 256) {
        int f = i >> 6, o = i & 63;
        float w1 = W[o*128 + f];
        float w2 = W[o*128 + 64 + f];
        Wm[f*OO + o]  = w1 - w2;
        W2s[f*OO + o] = w2;
    }
    __syncthreads();

    const int lane = threadIdx.x & 31, warp = threadIdx.x >> 5;
    const int p0 = blockIdx.x * 64 + warp * 8;

    for (int pp = 0; pp < 8; ++pp) {
        const int p = p0 + pp;
        const float* xr = x + (size_t)p * FF;
        float x0 = xr[lane], x1 = xr[lane + 32];
        xbuf[warp][lane] = x0; xbuf[warp][lane + 32] = x1;
        __syncwarp();

        // squared norm
        float s = x0*x0 + x1*x1;
        #pragma unroll
        for (int o = 16; o; o >>= 1) s += __shfl_xor_sync(FULLM, s, o);
        if (lane == 0) g_sq[p] = s;

        float u0 = 0.f, u1 = 0.f, v0 = 0.f, v1 = 0.f;
        #pragma unroll
        for (int f = 0; f < FF; ++f) {
            float xv = xbuf[warp][f];
            u0 = fmaf(Wm[f*OO + lane],       xv, u0);
            u1 = fmaf(Wm[f*OO + lane + 32],  xv, u1);
            v0 = fmaf(W2s[f*OO + lane],      xv, v0);
            v1 = fmaf(W2s[f*OO + lane + 32], xv, v1);
        }
        g_u[(size_t)p*OO + lane]      = u0;
        g_u[(size_t)p*OO + lane + 32] = u1;
        g_v[(size_t)p*OO + lane]      = v0;
        g_v[(size_t)p*OO + lane + 32] = v1;
        __syncwarp();
    }
}

// ---------------- KNN: 32 i-rows x 128 j-cols tiles, streaming top-20 ------------
// Warp w owns i-rows 4w..4w+3. Lane l owns j-cols 4l..4l+3 of each chunk.
// Smem XOR-swizzled at float4 granularity: conflict-free stores AND loads.
__global__ __launch_bounds__(256) void k_knn(const float* __restrict__ x) {
    __shared__ float xsi[FF*32];    // [f][i], swizzle col4 = i4 ^ (f&7)
    __shared__ float xsj[FF*128];   // [f][j], swizzle col4 = j4 ^ (f&31)

    const int b  = blockIdx.y;
    const int i0 = blockIdx.x * 32;
    const float* xb  = x    + (size_t)b * NN * FF;
    const float* sqb = g_sq + b * NN;
    const int tid = threadIdx.x, lane = tid & 31, warp = tid >> 5;

    // stage the i-tile (transposed, swizzled)
    #pragma unroll
    for (int r = 0; r < 2; ++r) {
        int id = tid + 256*r;
        int f = id & 63, i4 = id >> 6;          // i4 in [0,8)
        float4 vv;
        vv.x = xb[(i0 + 4*i4 + 0)*FF + f];
        vv.y = xb[(i0 + 4*i4 + 1)*FF + f];
        vv.z = xb[(i0 + 4*i4 + 2)*FF + f];
        vv.w = xb[(i0 + 4*i4 + 3)*FF + f];
        *(float4*)&xsi[f*32 + 4*(i4 ^ (f & 7))] = vv;
    }

    float sqi[4];
    #pragma unroll
    for (int r = 0; r < 4; ++r) sqi[r] = sqb[i0 + 4*warp + r];

    // streaming top-20 state: lanes 0..19 each hold one (val,idx) slot per row
    float bestv[4]   = {INFINITY, INFINITY, INFINITY, INFINITY};
    int   besti[4]   = {0, 0, 0, 0};
    float curmax[4]  = {INFINITY, INFINITY, INFINITY, INFINITY};
    int   maxlane[4] = {0, 0, 0, 0};

    for (int jc = 0; jc < NN/128; ++jc) {
        const int j0 = jc * 128;
        __syncthreads();
        #pragma unroll
        for (int r = 0; r < 8; ++r) {
            int id = tid + 256*r;
            int f = id & 63, j4 = id >> 6;      // j4 in [0,32)
            float4 vv;
            vv.x = xb[(j0 + 4*j4 + 0)*FF + f];
            vv.y = xb[(j0 + 4*j4 + 1)*FF + f];
            vv.z = xb[(j0 + 4*j4 + 2)*FF + f];
            vv.w = xb[(j0 + 4*j4 + 3)*FF + f];
            *(float4*)&xsj[f*128 + 4*(j4 ^ (f & 31))] = vv;
        }
        __syncthreads();

        float acc[4][4];
        #pragma unroll
        for (int r = 0; r < 4; ++r)
            #pragma unroll
            for (int q = 0; q < 4; ++q) acc[r][q] = 0.f;

        #pragma unroll
        for (int f = 0; f < FF; ++f) {
            float4 av = *(const float4*)&xsi[f*32  + 4*(warp ^ (f & 7))];
            float4 bv = *(const float4*)&xsj[f*128 + 4*(lane ^ (f & 31))];
            acc[0][0] = fmaf(av.x, bv.x, acc[0][0]);
            acc[0][1] = fmaf(av.x, bv.y, acc[0][1]);
            acc[0][2] = fmaf(av.x, bv.z, acc[0][2]);
            acc[0][3] = fmaf(av.x, bv.w, acc[0][3]);
            acc[1][0] = fmaf(av.y, bv.x, acc[1][0]);
            acc[1][1] = fmaf(av.y, bv.y, acc[1][1]);
            acc[1][2] = fmaf(av.y, bv.z, acc[1][2]);
            acc[1][3] = fmaf(av.y, bv.w, acc[1][3]);
            acc[2][0] = fmaf(av.z, bv.x, acc[2][0]);
            acc[2][1] = fmaf(av.z, bv.y, acc[2][1]);
            acc[2][2] = fmaf(av.z, bv.z, acc[2][2]);
            acc[2][3] = fmaf(av.z, bv.w, acc[2][3]);
            acc[3][0] = fmaf(av.w, bv.x, acc[3][0]);
            acc[3][1] = fmaf(av.w, bv.y, acc[3][1]);
            acc[3][2] = fmaf(av.w, bv.z, acc[3][2]);
            acc[3][3] = fmaf(av.w, bv.w, acc[3][3]);
        }

        float4 sq4 = *(const float4*)&sqb[j0 + 4*lane];
        const bool diag = (j0 >> 7) == (i0 >> 7);

        #pragma unroll
        for (int r = 0; r < 4; ++r) {
            const int ig = i0 + 4*warp + r;
            float d[4];
            d[0] = fmaf(-2.f, acc[r][0], sqi[r] + sq4.x);
            d[1] = fmaf(-2.f, acc[r][1], sqi[r] + sq4.y);
            d[2] = fmaf(-2.f, acc[r][2], sqi[r] + sq4.z);
            d[3] = fmaf(-2.f, acc[r][3], sqi[r] + sq4.w);
            if (diag) {
                #pragma unroll
                for (int q = 0; q < 4; ++q)
                    if (ig == j0 + 4*lane + q) d[q] = INFINITY;
            }
            #pragma unroll
            for (int q = 0; q < 4; ++q) {
                float v = d[q];
                unsigned m = __ballot_sync(FULLM, v < curmax[r]);
                while (m) {
                    int src  = __ffs(m) - 1;
                    float cv = __shfl_sync(FULLM, v, src);
                    int cj   = j0 + 4*src + q;
                    if (lane == maxlane[r]) { bestv[r] = cv; besti[r] = cj; }
                    // recompute (max, argmax-lane) over the 20 slots, lane-index tiebreak
                    float mv = (lane < KK) ? bestv[r] : -INFINITY;
                    int   ml = lane;
                    #pragma unroll
                    for (int s = 16; s; s >>= 1) {
                        float ov = __shfl_xor_sync(FULLM, mv, s);
                        int   ol = __shfl_xor_sync(FULLM, ml, s);
                        if (ov > mv || (ov == mv && ol < ml)) { mv = ov; ml = ol; }
                    }
                    curmax[r] = mv; maxlane[r] = ml;
                    if (lane == src) v = INFINITY;
                    m = __ballot_sync(FULLM, v < curmax[r]);
                }
            }
        }
    }

    #pragma unroll
    for (int r = 0; r < 4; ++r)
        if (lane < KK)
            g_idx[(size_t)(b*NN + i0 + 4*warp + r)*KK + lane] = besti[r];
}

// ---------------- fuse: h = u_n + v_j, per-(n,o) max/min, channel sums -----------
__global__ __launch_bounds__(256) void k_fuse() {
    const int tid = threadIdx.x, lane = tid & 31, warp = tid >> 5;
    const int p0 = blockIdx.x * 64 + warp * 8;
    float s0 = 0.f, s1 = 0.f, q0 = 0.f, q1 = 0.f;

    for (int pp = 0; pp < 8; ++pp) {
        const int p = p0 + pp;
        const int vbase = (p >> 12) << 18;   // (p/4096)*4096*64
        int myj = 0;
        if (lane < KK) myj = g_idx[(size_t)p*KK + lane];
        float u0 = g_u[(size_t)p*OO + lane];
        float u1 = g_u[(size_t)p*OO + lane + 32];
        float mx0 = -INFINITY, mx1 = -INFINITY, mn0 = INFINITY, mn1 = INFINITY;
        #pragma unroll
        for (int k = 0; k < KK; ++k) {
            int j = __shfl_sync(FULLM, myj, k);
            const float* vp = g_v + vbase + j*OO;
            float v0 = vp[lane], v1 = vp[lane + 32];
            float h0 = u0 + v0, h1 = u1 + v1;
            mx0 = fmaxf(mx0, h0); mn0 = fminf(mn0, h0);
            mx1 = fmaxf(mx1, h1); mn1 = fminf(mn1, h1);
            s0 += h0; q0 = fmaf(h0, h0, q0);
            s1 += h1; q1 = fmaf(h1, h1, q1);
        }
        g_hmax[(size_t)p*OO + lane]      = mx0;
        g_hmax[(size_t)p*OO + lane + 32] = mx1;
        g_hmin[(size_t)p*OO + lane]      = mn0;
        g_hmin[(size_t)p*OO + lane + 32] = mn1;
    }

    __shared__ float sb[8][OO], qb[8][OO];
    sb[warp][lane] = s0; sb[warp][lane + 32] = s1;
    qb[warp][lane] = q0; qb[warp][lane + 32] = q1;
    __syncthreads();
    if (tid < OO) {
        float a = 0.f, c = 0.f;
        #pragma unroll
        for (int w = 0; w < 8; ++w) { a += sb[w][tid]; c += qb[w][tid]; }
        atomicAdd(&g_sum[tid], (double)a);
        atomicAdd(&g_ssq[tid], (double)c);
    }
}

// ---------------- finalize BN affine params ----------------
__global__ void k_stats(const float* __restrict__ gamma, const float* __restrict__ beta) {
    int o = threadIdx.x;
    if (o < OO) {
        const double cnt = (double)NPTS * (double)KK;
        double m   = g_sum[o] / cnt;
        double var = g_ssq[o] / cnt - m * m;
        float a = gamma[o] * rsqrtf((float)var + 1e-5f);
        g_scale[o] = a;
        g_shift[o] = beta[o] - (float)m * a;
    }
}

// ---------------- apply BN + ReLU to the pooled extrema ----------------
__global__ __launch_bounds__(256) void k_final(float* __restrict__ out) {
    int t = blockIdx.x * 256 + threadIdx.x;          // 4 floats per thread
    float4 mx = ((const float4*)g_hmax)[t];
    float4 mn = ((const float4*)g_hmin)[t];
    int o = (t * 4) & 63;
    float a0 = g_scale[o+0], a1 = g_scale[o+1], a2 = g_scale[o+2], a3 = g_scale[o+3];
    float4 r;
    r.x = fmaxf(fmaf(a0, (a0 >= 0.f) ? mx.x : mn.x, g_shift[o+0]), 0.f);
    r.y = fmaxf(fmaf(a1, (a1 >= 0.f) ? mx.y : mn.y, g_shift[o+1]), 0.f);
    r.z = fmaxf(fmaf(a2, (a2 >= 0.f) ? mx.z : mn.z, g_shift[o+2]), 0.f);
    r.w = fmaxf(fmaf(a3, (a3 >= 0.f) ? mx.w : mn.w, g_shift[o+3]), 0.f);
    ((float4*)out)[t] = r;
}

extern "C" void kernel_launch(void* const* d_in, const int* in_sizes, int n_in,
                              void* d_out, int out_size) {
    const float* x     = (const float*)d_in[0];
    const float* W     = (const float*)d_in[1];
    // d_in[2] (conv bias b) cancels exactly under BatchNorm: unused.
    const float* gamma = (const float*)d_in[3];
    const float* beta  = (const float*)d_in[4];
    float* out = (float*)d_out;

    k_zero <<<1, 64>>>();
    k_uv   <<<NPTS/64, 256>>>(x, W);
    k_knn  <<<dim3(NN/32, BB), 256>>>(x);
    k_fuse <<<NPTS/64, 256>>>();
    k_stats<<<1, 64>>>(gamma, beta);
    k_final<<<NPTS*OO/1024, 256>>>(out);
}

// round 2
// speedup vs baseline: 1.0596x; 1.0596x over previous
#include <cuda_runtime.h>
#include <math.h>
#include <stdint.h>

#define BB 8
#define NN 4096
#define FF 64
#define OO 64
#define KK 20
#define NPTS (BB*NN)
#define FULLM 0xFFFFFFFFu

// ---------------- scratch (device globals: no allocation allowed) ----------------
__device__ float  g_sq[NPTS];
__device__ float  g_u[NPTS*OO];
__device__ float  g_v[NPTS*OO];
__device__ int    g_idx[NPTS*KK];
__device__ float  g_hmax[NPTS*OO];
__device__ float  g_hmin[NPTS*OO];
__device__ double g_sum[OO];
__device__ double g_ssq[OO];
__device__ float  g_scale[OO];
__device__ float  g_shift[OO];

// packed dual-fp32 FMA (Blackwell f32x2 pipe, PTX-only — 2x FFMA throughput)
__device__ __forceinline__ void ffma2(unsigned long long &acc,
                                      unsigned long long a,
                                      unsigned long long b) {
    asm("fma.rn.f32x2 %0, %1, %2, %0;" : "+l"(acc) : "l"(a), "l"(b));
}
__device__ __forceinline__ unsigned long long dup2(float v) {
    unsigned long long r;
    asm("mov.b64 %0, {%1, %1};" : "=l"(r) : "f"(v));
    return r;
}
__device__ __forceinline__ void unpack2(unsigned long long p, float &lo, float &hi) {
    asm("mov.b64 {%0, %1}, %2;" : "=f"(lo), "=f"(hi) : "l"(p));
}

// ---------------- zero the stat accumulators (graph replays reuse globals) -------
__global__ void k_zero() {
    int t = threadIdx.x;
    if (t < OO) { g_sum[t] = 0.0; g_ssq[t] = 0.0; }
}

// ---------------- u = x*(W1-W2)^T, v = x*W2^T, plus squared norms ----------------
__global__ __launch_bounds__(256) void k_uv(const float* __restrict__ x,
                                            const float* __restrict__ W) {
    __shared__ float Wm[FF*OO];   // (W1 - W2)[f][o]
    __shared__ float W2s[FF*OO];  // W2[f][o]
    __shared__ float xbuf[8][FF];

    for (int i = threadIdx.x; i < FF*OO; i += 256) {
        int f = i >> 6, o = i & 63;
        float w1 = W[o*128 + f];
        float w2 = W[o*128 + 64 + f];
        Wm[f*OO + o]  = w1 - w2;
        W2s[f*OO + o] = w2;
    }
    __syncthreads();

    const int lane = threadIdx.x & 31, warp = threadIdx.x >> 5;
    const int p0 = blockIdx.x * 64 + warp * 8;

    for (int pp = 0; pp < 8; ++pp) {
        const int p = p0 + pp;
        const float* xr = x + (size_t)p * FF;
        float x0 = xr[lane], x1 = xr[lane + 32];
        xbuf[warp][lane] = x0; xbuf[warp][lane + 32] = x1;
        __syncwarp();

        float s = x0*x0 + x1*x1;
        #pragma unroll
        for (int o = 16; o; o >>= 1) s += __shfl_xor_sync(FULLM, s, o);
        if (lane == 0) g_sq[p] = s;

        float u0 = 0.f, u1 = 0.f, v0 = 0.f, v1 = 0.f;
        #pragma unroll
        for (int f = 0; f < FF; ++f) {
            float xv = xbuf[warp][f];
            u0 = fmaf(Wm[f*OO + lane],       xv, u0);
            u1 = fmaf(Wm[f*OO + lane + 32],  xv, u1);
            v0 = fmaf(W2s[f*OO + lane],      xv, v0);
            v1 = fmaf(W2s[f*OO + lane + 32], xv, v1);
        }
        g_u[(size_t)p*OO + lane]      = u0;
        g_u[(size_t)p*OO + lane + 32] = u1;
        g_v[(size_t)p*OO + lane]      = v0;
        g_v[(size_t)p*OO + lane + 32] = v1;
        __syncwarp();
    }
}

// ---------------- KNN: 64 i-rows x 128 j-cols tiles, f32x2 packed FMA ------------
// Warp w owns i-rows 8w..8w+7 (register pairs along i). Lane l owns j-cols 4l..4l+3.
// xsi: [f][i] swizzled chunk4 = i4 ^ (f&15); av loads are warp-uniform broadcasts
// read as ulonglong2 (natural b64 row-pairs, zero packing movs).
// xsj: [f][j] swizzled chunk4 = j4 ^ (f&31); conflict-free float4 both directions.
__global__ __launch_bounds__(256, 2) void k_knn(const float* __restrict__ x) {
    __shared__ __align__(16) float xsi[FF*64];    // 16 KB
    __shared__ __align__(16) float xsj[FF*128];   // 32 KB

    const int b  = blockIdx.y;
    const int i0 = blockIdx.x * 64;
    const float* xb  = x    + (size_t)b * NN * FF;
    const float* sqb = g_sq + b * NN;
    const int tid = threadIdx.x, lane = tid & 31, warp = tid >> 5;

    // stage the i-tile (transposed, swizzled)
    #pragma unroll
    for (int r = 0; r < 4; ++r) {
        int id = tid + 256*r;
        int f = id & 63, i4 = id >> 6;          // i4 in [0,16)
        float4 vv;
        vv.x = xb[(i0 + 4*i4 + 0)*FF + f];
        vv.y = xb[(i0 + 4*i4 + 1)*FF + f];
        vv.z = xb[(i0 + 4*i4 + 2)*FF + f];
        vv.w = xb[(i0 + 4*i4 + 3)*FF + f];
        *(float4*)&xsi[f*64 + 4*(i4 ^ (f & 15))] = vv;
    }

    float sqi[8];
    #pragma unroll
    for (int r = 0; r < 8; ++r) sqi[r] = sqb[i0 + 8*warp + r];

    // streaming top-20 state (per i-row): lanes 0..19 hold one (val,idx) slot
    float bestv[8], curmax[8];
    int   besti[8], maxlane[8];
    #pragma unroll
    for (int r = 0; r < 8; ++r) {
        bestv[r] = INFINITY; curmax[r] = INFINITY; besti[r] = 0; maxlane[r] = 0;
    }

    for (int jc = 0; jc < NN/128; ++jc) {
        const int j0 = jc * 128;
        __syncthreads();
        #pragma unroll
        for (int r = 0; r < 8; ++r) {
            int id = tid + 256*r;
            int f = id & 63, j4 = id >> 6;      // j4 in [0,32)
            float4 vv;
            vv.x = xb[(j0 + 4*j4 + 0)*FF + f];
            vv.y = xb[(j0 + 4*j4 + 1)*FF + f];
            vv.z = xb[(j0 + 4*j4 + 2)*FF + f];
            vv.w = xb[(j0 + 4*j4 + 3)*FF + f];
            *(float4*)&xsj[f*128 + 4*(j4 ^ (f & 31))] = vv;
        }
        __syncthreads();

        // 16 packed accumulators: accP[m][q] = rows (2m, 2m+1), col q
        unsigned long long accP[4][4];
        #pragma unroll
        for (int m = 0; m < 4; ++m)
            #pragma unroll
            for (int q = 0; q < 4; ++q) accP[m][q] = 0ull;

        #pragma unroll 16
        for (int f = 0; f < FF; ++f) {
            // warp-uniform A row-pairs (broadcast LDS.128 as 2x b64)
            ulonglong2 aA = *(const ulonglong2*)&xsi[f*64 + 4*((2*warp)     ^ (f & 15))];
            ulonglong2 aB = *(const ulonglong2*)&xsi[f*64 + 4*((2*warp + 1) ^ (f & 15))];
            float4 bv = *(const float4*)&xsj[f*128 + 4*(lane ^ (f & 31))];
            unsigned long long b0 = dup2(bv.x), b1 = dup2(bv.y),
                               b2 = dup2(bv.z), b3 = dup2(bv.w);
            ffma2(accP[0][0], aA.x, b0); ffma2(accP[0][1], aA.x, b1);
            ffma2(accP[0][2], aA.x, b2); ffma2(accP[0][3], aA.x, b3);
            ffma2(accP[1][0], aA.y, b0); ffma2(accP[1][1], aA.y, b1);
            ffma2(accP[1][2], aA.y, b2); ffma2(accP[1][3], aA.y, b3);
            ffma2(accP[2][0], aB.x, b0); ffma2(accP[2][1], aB.x, b1);
            ffma2(accP[2][2], aB.x, b2); ffma2(accP[2][3], aB.x, b3);
            ffma2(accP[3][0], aB.y, b0); ffma2(accP[3][1], aB.y, b1);
            ffma2(accP[3][2], aB.y, b2); ffma2(accP[3][3], aB.y, b3);
        }

        float4 sq4 = *(const float4*)&sqb[j0 + 4*lane];
        const float sqj[4] = {sq4.x, sq4.y, sq4.z, sq4.w};

        #pragma unroll
        for (int m = 0; m < 4; ++m) {
            float dot[2][4];
            #pragma unroll
            for (int q = 0; q < 4; ++q) unpack2(accP[m][q], dot[0][q], dot[1][q]);

            #pragma unroll
            for (int h = 0; h < 2; ++h) {
                const int r  = 2*m + h;
                const int ig = i0 + 8*warp + r;
                const bool diag = (ig >> 7) == (j0 >> 7);
                float d[4];
                #pragma unroll
                for (int q = 0; q < 4; ++q)
                    d[q] = fmaf(-2.f, dot[h][q], sqi[r] + sqj[q]);
                if (diag) {
                    #pragma unroll
                    for (int q = 0; q < 4; ++q)
                        if (ig == j0 + 4*lane + q) d[q] = INFINITY;
                }
                #pragma unroll
                for (int q = 0; q < 4; ++q) {
                    float v = d[q];
                    unsigned mmask = __ballot_sync(FULLM, v < curmax[r]);
                    while (mmask) {
                        int src  = __ffs(mmask) - 1;
                        float cv = __shfl_sync(FULLM, v, src);
                        int cj   = j0 + 4*src + q;
                        if (lane == maxlane[r]) { bestv[r] = cv; besti[r] = cj; }
                        float mv = (lane < KK) ? bestv[r] : -INFINITY;
                        int   ml = lane;
                        #pragma unroll
                        for (int s = 16; s; s >>= 1) {
                            float ov = __shfl_xor_sync(FULLM, mv, s);
                            int   ol = __shfl_xor_sync(FULLM, ml, s);
                            if (ov > mv || (ov == mv && ol < ml)) { mv = ov; ml = ol; }
                        }
                        curmax[r] = mv; maxlane[r] = ml;
                        if (lane == src) v = INFINITY;
                        mmask = __ballot_sync(FULLM, v < curmax[r]);
                    }
                }
            }
        }
    }

    #pragma unroll
    for (int r = 0; r < 8; ++r)
        if (lane < KK)
            g_idx[(size_t)(b*NN + i0 + 8*warp + r)*KK + lane] = besti[r];
}

// ---------------- fuse: h = u_n + v_j, per-(n,o) max/min, channel sums -----------
__global__ __launch_bounds__(256) void k_fuse() {
    const int tid = threadIdx.x, lane = tid & 31, warp = tid >> 5;
    const int p0 = blockIdx.x * 64 + warp * 8;
    float s0 = 0.f, s1 = 0.f, q0 = 0.f, q1 = 0.f;

    for (int pp = 0; pp < 8; ++pp) {
        const int p = p0 + pp;
        const int vbase = (p >> 12) << 18;   // (p/4096)*4096*64
        int myj = 0;
        if (lane < KK) myj = g_idx[(size_t)p*KK + lane];
        float u0 = g_u[(size_t)p*OO + lane];
        float u1 = g_u[(size_t)p*OO + lane + 32];
        float mx0 = -INFINITY, mx1 = -INFINITY, mn0 = INFINITY, mn1 = INFINITY;
        #pragma unroll
        for (int k = 0; k < KK; ++k) {
            int j = __shfl_sync(FULLM, myj, k);
            const float* vp = g_v + vbase + j*OO;
            float v0 = vp[lane], v1 = vp[lane + 32];
            float h0 = u0 + v0, h1 = u1 + v1;
            mx0 = fmaxf(mx0, h0); mn0 = fminf(mn0, h0);
            mx1 = fmaxf(mx1, h1); mn1 = fminf(mn1, h1);
            s0 += h0; q0 = fmaf(h0, h0, q0);
            s1 += h1; q1 = fmaf(h1, h1, q1);
        }
        g_hmax[(size_t)p*OO + lane]      = mx0;
        g_hmax[(size_t)p*OO + lane + 32] = mx1;
        g_hmin[(size_t)p*OO + lane]      = mn0;
        g_hmin[(size_t)p*OO + lane + 32] = mn1;
    }

    __shared__ float sb[8][OO], qb[8][OO];
    sb[warp][lane] = s0; sb[warp][lane + 32] = s1;
    qb[warp][lane] = q0; qb[warp][lane + 32] = q1;
    __syncthreads();
    if (tid < OO) {
        float a = 0.f, c = 0.f;
        #pragma unroll
        for (int w = 0; w < 8; ++w) { a += sb[w][tid]; c += qb[w][tid]; }
        atomicAdd(&g_sum[tid], (double)a);
        atomicAdd(&g_ssq[tid], (double)c);
    }
}

// ---------------- finalize BN affine params ----------------
__global__ void k_stats(const float* __restrict__ gamma, const float* __restrict__ beta) {
    int o = threadIdx.x;
    if (o < OO) {
        const double cnt = (double)NPTS * (double)KK;
        double m   = g_sum[o] / cnt;
        double var = g_ssq[o] / cnt - m * m;
        float a = gamma[o] * rsqrtf((float)var + 1e-5f);
        g_scale[o] = a;
        g_shift[o] = beta[o] - (float)m * a;
    }
}

// ---------------- apply BN + ReLU to the pooled extrema ----------------
__global__ __launch_bounds__(256) void k_final(float* __restrict__ out) {
    int t = blockIdx.x * 256 + threadIdx.x;          // 4 floats per thread
    float4 mx = ((const float4*)g_hmax)[t];
    float4 mn = ((const float4*)g_hmin)[t];
    int o = (t * 4) & 63;
    float a0 = g_scale[o+0], a1 = g_scale[o+1], a2 = g_scale[o+2], a3 = g_scale[o+3];
    float4 r;
    r.x = fmaxf(fmaf(a0, (a0 >= 0.f) ? mx.x : mn.x, g_shift[o+0]), 0.f);
    r.y = fmaxf(fmaf(a1, (a1 >= 0.f) ? mx.y : mn.y, g_shift[o+1]), 0.f);
    r.z = fmaxf(fmaf(a2, (a2 >= 0.f) ? mx.z : mn.z, g_shift[o+2]), 0.f);
    r.w = fmaxf(fmaf(a3, (a3 >= 0.f) ? mx.w : mn.w, g_shift[o+3]), 0.f);
    ((float4*)out)[t] = r;
}

extern "C" void kernel_launch(void* const* d_in, const int* in_sizes, int n_in,
                              void* d_out, int out_size) {
    const float* x     = (const float*)d_in[0];
    const float* W     = (const float*)d_in[1];
    // d_in[2] (conv bias b) cancels exactly under BatchNorm: unused.
    const float* gamma = (const float*)d_in[3];
    const float* beta  = (const float*)d_in[4];
    float* out = (float*)d_out;

    k_zero <<<1, 64>>>();
    k_uv   <<<NPTS/64, 256>>>(x, W);
    k_knn  <<<dim3(NN/64, BB), 256>>>(x);
    k_fuse <<<NPTS/64, 256>>>();
    k_stats<<<1, 64>>>(gamma, beta);
    k_final<<<NPTS*OO/1024, 256>>>(out);
}

// round 3
// speedup vs baseline: 1.3267x; 1.2521x over previous
#include <cuda_runtime.h>
#include <math.h>
#include <stdint.h>

#define BB 8
#define NN 4096
#define FF 64
#define OO 64
#define KK 20
#define NPTS (BB*NN)
#define FULLM 0xFFFFFFFFu

// ---------------- scratch (device globals: no allocation allowed) ----------------
__device__ float  g_sq[NPTS];
__device__ float  g_u[NPTS*OO];
__device__ float  g_v[NPTS*OO];
__device__ int    g_idx[NPTS*KK];
__device__ float  g_hmax[NPTS*OO];
__device__ float  g_hmin[NPTS*OO];
__device__ double g_sum[OO];
__device__ double g_ssq[OO];
__device__ float  g_scale[OO];
__device__ float  g_shift[OO];
__device__ int    g_ctr;

// packed dual-fp32 FMA (Blackwell f32x2 pipe, PTX-only)
__device__ __forceinline__ void ffma2(unsigned long long &acc,
                                      unsigned long long a,
                                      unsigned long long b) {
    asm("fma.rn.f32x2 %0, %1, %2, %0;" : "+l"(acc) : "l"(a), "l"(b));
}
__device__ __forceinline__ unsigned long long dup2(float v) {
    unsigned long long r;
    asm("mov.b64 %0, {%1, %1};" : "=l"(r) : "f"(v));
    return r;
}
__device__ __forceinline__ void unpack2(unsigned long long p, float &lo, float &hi) {
    asm("mov.b64 {%0, %1}, %2;" : "=f"(lo), "=f"(hi) : "l"(p));
}

// ---------------- u = x*(W1-W2)^T, v = x*W2^T, norms; block0 zeroes stats --------
__global__ __launch_bounds__(256) void k_uv(const float* __restrict__ x,
                                            const float* __restrict__ W) {
    if (blockIdx.x == 0) {
        if (threadIdx.x < OO) { g_sum[threadIdx.x] = 0.0; g_ssq[threadIdx.x] = 0.0; }
        if (threadIdx.x == 0) g_ctr = 0;
    }

    __shared__ float Wm[FF*OO];   // (W1 - W2)[f][o]
    __shared__ float W2s[FF*OO];  // W2[f][o]
    __shared__ float xbuf[8][FF];

    for (int i = threadIdx.x; i < FF*OO; i += 256) {
        int f = i >> 6, o = i & 63;
        float w1 = W[o*128 + f];
        float w2 = W[o*128 + 64 + f];
        Wm[f*OO + o]  = w1 - w2;
        W2s[f*OO + o] = w2;
    }
    __syncthreads();

    const int lane = threadIdx.x & 31, warp = threadIdx.x >> 5;
    const int p0 = blockIdx.x * 64 + warp * 8;

    for (int pp = 0; pp < 8; ++pp) {
        const int p = p0 + pp;
        const float* xr = x + (size_t)p * FF;
        float x0 = xr[lane], x1 = xr[lane + 32];
        xbuf[warp][lane] = x0; xbuf[warp][lane + 32] = x1;
        __syncwarp();

        float s = x0*x0 + x1*x1;
        #pragma unroll
        for (int o = 16; o; o >>= 1) s += __shfl_xor_sync(FULLM, s, o);
        if (lane == 0) g_sq[p] = s;

        float u0 = 0.f, u1 = 0.f, v0 = 0.f, v1 = 0.f;
        #pragma unroll
        for (int f = 0; f < FF; ++f) {
            float xv = xbuf[warp][f];
            u0 = fmaf(Wm[f*OO + lane],       xv, u0);
            u1 = fmaf(Wm[f*OO + lane + 32],  xv, u1);
            v0 = fmaf(W2s[f*OO + lane],      xv, v0);
            v1 = fmaf(W2s[f*OO + lane + 32], xv, v1);
        }
        g_u[(size_t)p*OO + lane]      = u0;
        g_u[(size_t)p*OO + lane + 32] = u1;
        g_v[(size_t)p*OO + lane]      = v0;
        g_v[(size_t)p*OO + lane + 32] = v1;
        __syncwarp();
    }
}

// ---------------- KNN: 64 i-rows x 128 j-cols tiles, f32x2 FMA, sorted top-20 ----
// Warp w owns i-rows 8w..8w+7. Lane l owns j-cols 4l..4l+3.
// Top-20 kept SORTED ascending across lanes 0..19 -> insert is a shift-up,
// threshold update is max(bestv[18], cv): ~80-cycle chain per insert.
__global__ __launch_bounds__(256, 2) void k_knn(const float* __restrict__ x) {
    __shared__ __align__(16) float xsi[FF*64];    // 16 KB
    __shared__ __align__(16) float xsj[FF*128];   // 32 KB

    const int b  = blockIdx.y;
    const int i0 = blockIdx.x * 64;
    const float* xb  = x    + (size_t)b * NN * FF;
    const float* sqb = g_sq + b * NN;
    const int tid = threadIdx.x, lane = tid & 31, warp = tid >> 5;

    // stage the i-tile (transposed, swizzled)
    #pragma unroll
    for (int r = 0; r < 4; ++r) {
        int id = tid + 256*r;
        int f = id & 63, i4 = id >> 6;          // i4 in [0,16)
        float4 vv;
        vv.x = xb[(i0 + 4*i4 + 0)*FF + f];
        vv.y = xb[(i0 + 4*i4 + 1)*FF + f];
        vv.z = xb[(i0 + 4*i4 + 2)*FF + f];
        vv.w = xb[(i0 + 4*i4 + 3)*FF + f];
        *(float4*)&xsi[f*64 + 4*(i4 ^ (f & 15))] = vv;
    }

    float sqi[8];
    #pragma unroll
    for (int r = 0; r < 8; ++r) sqi[r] = sqb[i0 + 8*warp + r];

    // sorted top-20: lanes 0..19 hold ascending (val, idx); curmax = slot-19 value
    float bestv[8], curmax[8];
    int   besti[8];
    #pragma unroll
    for (int r = 0; r < 8; ++r) { bestv[r] = INFINITY; curmax[r] = INFINITY; besti[r] = 0; }

    for (int jc = 0; jc < NN/128; ++jc) {
        const int j0 = jc * 128;
        __syncthreads();
        #pragma unroll
        for (int r = 0; r < 8; ++r) {
            int id = tid + 256*r;
            int f = id & 63, j4 = id >> 6;      // j4 in [0,32)
            float4 vv;
            vv.x = xb[(j0 + 4*j4 + 0)*FF + f];
            vv.y = xb[(j0 + 4*j4 + 1)*FF + f];
            vv.z = xb[(j0 + 4*j4 + 2)*FF + f];
            vv.w = xb[(j0 + 4*j4 + 3)*FF + f];
            *(float4*)&xsj[f*128 + 4*(j4 ^ (f & 31))] = vv;
        }
        __syncthreads();

        unsigned long long accP[4][4];
        #pragma unroll
        for (int m = 0; m < 4; ++m)
            #pragma unroll
            for (int q = 0; q < 4; ++q) accP[m][q] = 0ull;

        #pragma unroll 16
        for (int f = 0; f < FF; ++f) {
            ulonglong2 aA = *(const ulonglong2*)&xsi[f*64 + 4*((2*warp)     ^ (f & 15))];
            ulonglong2 aB = *(const ulonglong2*)&xsi[f*64 + 4*((2*warp + 1) ^ (f & 15))];
            float4 bv = *(const float4*)&xsj[f*128 + 4*(lane ^ (f & 31))];
            unsigned long long b0 = dup2(bv.x), b1 = dup2(bv.y),
                               b2 = dup2(bv.z), b3 = dup2(bv.w);
            ffma2(accP[0][0], aA.x, b0); ffma2(accP[0][1], aA.x, b1);
            ffma2(accP[0][2], aA.x, b2); ffma2(accP[0][3], aA.x, b3);
            ffma2(accP[1][0], aA.y, b0); ffma2(accP[1][1], aA.y, b1);
            ffma2(accP[1][2], aA.y, b2); ffma2(accP[1][3], aA.y, b3);
            ffma2(accP[2][0], aB.x, b0); ffma2(accP[2][1], aB.x, b1);
            ffma2(accP[2][2], aB.x, b2); ffma2(accP[2][3], aB.x, b3);
            ffma2(accP[3][0], aB.y, b0); ffma2(accP[3][1], aB.y, b1);
            ffma2(accP[3][2], aB.y, b2); ffma2(accP[3][3], aB.y, b3);
        }

        float4 sq4 = *(const float4*)&sqb[j0 + 4*lane];
        const float sqj[4] = {sq4.x, sq4.y, sq4.z, sq4.w};

        #pragma unroll
        for (int m = 0; m < 4; ++m) {
            float dot[2][4];
            #pragma unroll
            for (int q = 0; q < 4; ++q) unpack2(accP[m][q], dot[0][q], dot[1][q]);

            #pragma unroll
            for (int h = 0; h < 2; ++h) {
                const int r  = 2*m + h;
                const int ig = i0 + 8*warp + r;
                const bool diag = (ig >> 7) == (j0 >> 7);
                float d[4];
                #pragma unroll
                for (int q = 0; q < 4; ++q)
                    d[q] = fmaf(-2.f, dot[h][q], sqi[r] + sqj[q]);
                if (diag) {
                    #pragma unroll
                    for (int q = 0; q < 4; ++q)
                        if (ig == j0 + 4*lane + q) d[q] = INFINITY;
                }
                // fast skip: one ballot when no lane has any candidate
                float dmin = fminf(fminf(d[0], d[1]), fminf(d[2], d[3]));
                if (__ballot_sync(FULLM, dmin < curmax[r])) {
                    #pragma unroll
                    for (int q = 0; q < 4; ++q) {
                        float v = d[q];
                        unsigned mmask = __ballot_sync(FULLM, v < curmax[r]);
                        while (mmask) {
                            int src  = __ffs(mmask) - 1;
                            float cv = __shfl_sync(FULLM, v, src);
                            int   cj = j0 + 4*src + q;
                            // off-critical-path helpers
                            float upv = __shfl_up_sync(FULLM, bestv[r], 1);
                            int   upi = __shfl_up_sync(FULLM, besti[r], 1);
                            float p18 = __shfl_sync(FULLM, bestv[r], 18);
                            bool shift = (lane < KK) && (bestv[r] > cv);
                            unsigned pm = __ballot_sync(FULLM, shift);
                            int first = __ffs(pm) - 1;
                            if (shift) {
                                bestv[r] = (lane == first) ? cv : upv;
                                besti[r] = (lane == first) ? cj : upi;
                            }
                            curmax[r] = fmaxf(p18, cv);
                            if (lane == src) v = INFINITY;
                            mmask = __ballot_sync(FULLM, v < curmax[r]);
                        }
                    }
                }
            }
        }
    }

    #pragma unroll
    for (int r = 0; r < 8; ++r)
        if (lane < KK)
            g_idx[(size_t)(b*NN + i0 + 8*warp + r)*KK + lane] = besti[r];
}

// ---------------- fuse: h = u_n + v_j, max/min, channel sums; last block -> BN ---
__global__ __launch_bounds__(256) void k_fuse(const float* __restrict__ gamma,
                                              const float* __restrict__ beta) {
    const int tid = threadIdx.x, lane = tid & 31, warp = tid >> 5;
    const int p0 = blockIdx.x * 64 + warp * 8;
    float s0 = 0.f, s1 = 0.f, q0 = 0.f, q1 = 0.f;

    for (int pp = 0; pp < 8; ++pp) {
        const int p = p0 + pp;
        const int vbase = (p >> 12) << 18;   // (p/4096)*4096*64
        int myj = 0;
        if (lane < KK) myj = g_idx[(size_t)p*KK + lane];
        float u0 = g_u[(size_t)p*OO + lane];
        float u1 = g_u[(size_t)p*OO + lane + 32];
        float mx0 = -INFINITY, mx1 = -INFINITY, mn0 = INFINITY, mn1 = INFINITY;
        #pragma unroll
        for (int k = 0; k < KK; ++k) {
            int j = __shfl_sync(FULLM, myj, k);
            const float* vp = g_v + vbase + j*OO;
            float v0 = vp[lane], v1 = vp[lane + 32];
            float h0 = u0 + v0, h1 = u1 + v1;
            mx0 = fmaxf(mx0, h0); mn0 = fminf(mn0, h0);
            mx1 = fmaxf(mx1, h1); mn1 = fminf(mn1, h1);
            s0 += h0; q0 = fmaf(h0, h0, q0);
            s1 += h1; q1 = fmaf(h1, h1, q1);
        }
        g_hmax[(size_t)p*OO + lane]      = mx0;
        g_hmax[(size_t)p*OO + lane + 32] = mx1;
        g_hmin[(size_t)p*OO + lane]      = mn0;
        g_hmin[(size_t)p*OO + lane + 32] = mn1;
    }

    __shared__ float sb[8][OO], qb[8][OO];
    sb[warp][lane] = s0; sb[warp][lane + 32] = s1;
    qb[warp][lane] = q0; qb[warp][lane + 32] = q1;
    __syncthreads();
    if (tid < OO) {
        float a = 0.f, c = 0.f;
        #pragma unroll
        for (int w = 0; w < 8; ++w) { a += sb[w][tid]; c += qb[w][tid]; }
        atomicAdd(&g_sum[tid], (double)a);
        atomicAdd(&g_ssq[tid], (double)c);
    }
    __syncthreads();

    // last block computes the BN affine params
    __shared__ int amLast;
    if (tid == 0) {
        __threadfence();
        amLast = (atomicAdd(&g_ctr, 1) == (int)gridDim.x - 1);
    }
    __syncthreads();
    if (amLast) {
        __threadfence();
        if (tid < OO) {
            const double cnt = (double)NPTS * (double)KK;
            double m   = g_sum[tid] / cnt;
            double var = g_ssq[tid] / cnt - m * m;
            float a = gamma[tid] * rsqrtf((float)var + 1e-5f);
            g_scale[tid] = a;
            g_shift[tid] = beta[tid] - (float)m * a;
        }
    }
}

// ---------------- apply BN + ReLU to the pooled extrema ----------------
__global__ __launch_bounds__(256) void k_final(float* __restrict__ out) {
    int t = blockIdx.x * 256 + threadIdx.x;          // 4 floats per thread
    float4 mx = ((const float4*)g_hmax)[t];
    float4 mn = ((const float4*)g_hmin)[t];
    int o = (t * 4) & 63;
    float a0 = g_scale[o+0], a1 = g_scale[o+1], a2 = g_scale[o+2], a3 = g_scale[o+3];
    float4 r;
    r.x = fmaxf(fmaf(a0, (a0 >= 0.f) ? mx.x : mn.x, g_shift[o+0]), 0.f);
    r.y = fmaxf(fmaf(a1, (a1 >= 0.f) ? mx.y : mn.y, g_shift[o+1]), 0.f);
    r.z = fmaxf(fmaf(a2, (a2 >= 0.f) ? mx.z : mn.z, g_shift[o+2]), 0.f);
    r.w = fmaxf(fmaf(a3, (a3 >= 0.f) ? mx.w : mn.w, g_shift[o+3]), 0.f);
    ((float4*)out)[t] = r;
}

extern "C" void kernel_launch(void* const* d_in, const int* in_sizes, int n_in,
                              void* d_out, int out_size) {
    const float* x     = (const float*)d_in[0];
    const float* W     = (const float*)d_in[1];
    // d_in[2] (conv bias b) cancels exactly under BatchNorm: unused.
    const float* gamma = (const float*)d_in[3];
    const float* beta  = (const float*)d_in[4];
    float* out = (float*)d_out;

    k_uv   <<<NPTS/64, 256>>>(x, W);
    k_knn  <<<dim3(NN/64, BB), 256>>>(x);
    k_fuse <<<NPTS/64, 256>>>(gamma, beta);
    k_final<<<NPTS*OO/1024, 256>>>(out);
}

// round 5
// speedup vs baseline: 1.3777x; 1.0384x over previous
#include <cuda_runtime.h>
#include <math.h>
#include <stdint.h>

#define BB 8
#define NN 4096
#define FF 64
#define OO 64
#define KK 20
#define NPTS (BB*NN)
#define FULLM 0xFFFFFFFFu
#define JCH 128
#define NCHUNK (NN/JCH)

// ---------------- scratch (device globals: no allocation allowed) ----------------
__device__ float  g_sq[NPTS];
__device__ float  g_u[NPTS*OO];
__device__ float  g_v[NPTS*OO];
__device__ int    g_idx[NPTS*KK];
__device__ float  g_hmax[NPTS*OO];
__device__ float  g_hmin[NPTS*OO];
__device__ double g_sum[OO];
__device__ double g_ssq[OO];
__device__ float  g_scale[OO];
__device__ float  g_shift[OO];
__device__ int    g_ctr;

// packed dual-fp32 FMA (Blackwell f32x2 pipe, PTX-only)
__device__ __forceinline__ void ffma2(unsigned long long &acc,
                                      unsigned long long a,
                                      unsigned long long b) {
    asm("fma.rn.f32x2 %0, %1, %2, %0;" : "+l"(acc) : "l"(a), "l"(b));
}
__device__ __forceinline__ unsigned long long dup2(float v) {
    unsigned long long r;
    asm("mov.b64 %0, {%1, %1};" : "=l"(r) : "f"(v));
    return r;
}
__device__ __forceinline__ void unpack2(unsigned long long p, float &lo, float &hi) {
    asm("mov.b64 {%0, %1}, %2;" : "=f"(lo), "=f"(hi) : "l"(p));
}

// ---------------- u = x*(W1-W2)^T, v = x*W2^T, norms; block0 zeroes stats --------
__global__ __launch_bounds__(256) void k_uv(const float* __restrict__ x,
                                            const float* __restrict__ W) {
    if (blockIdx.x == 0) {
        if (threadIdx.x < OO) { g_sum[threadIdx.x] = 0.0; g_ssq[threadIdx.x] = 0.0; }
        if (threadIdx.x == 0) g_ctr = 0;
    }

    __shared__ float Wm[FF*OO];   // (W1 - W2)[f][o]
    __shared__ float W2s[FF*OO];  // W2[f][o]
    __shared__ float xbuf[8][FF];

    for (int i = threadIdx.x; i < FF*OO; i += 256) {
        int f = i >> 6, o = i & 63;
        float w1 = W[o*128 + f];
        float w2 = W[o*128 + 64 + f];
        Wm[f*OO + o]  = w1 - w2;
        W2s[f*OO + o] = w2;
    }
    __syncthreads();

    const int lane = threadIdx.x & 31, warp = threadIdx.x >> 5;
    const int p0 = blockIdx.x * 64 + warp * 8;

    for (int pp = 0; pp < 8; ++pp) {
        const int p = p0 + pp;
        const float* xr = x + (size_t)p * FF;
        float x0 = xr[lane], x1 = xr[lane + 32];
        xbuf[warp][lane] = x0; xbuf[warp][lane + 32] = x1;
        __syncwarp();

        float s = x0*x0 + x1*x1;
        #pragma unroll
        for (int o = 16; o; o >>= 1) s += __shfl_xor_sync(FULLM, s, o);
        if (lane == 0) g_sq[p] = s;

        float u0 = 0.f, u1 = 0.f, v0 = 0.f, v1 = 0.f;
        #pragma unroll
        for (int f = 0; f < FF; ++f) {
            float xv = xbuf[warp][f];
            u0 = fmaf(Wm[f*OO + lane],       xv, u0);
            u1 = fmaf(Wm[f*OO + lane + 32],  xv, u1);
            v0 = fmaf(W2s[f*OO + lane],      xv, v0);
            v1 = fmaf(W2s[f*OO + lane + 32], xv, v1);
        }
        g_u[(size_t)p*OO + lane]      = u0;
        g_u[(size_t)p*OO + lane + 32] = u1;
        g_v[(size_t)p*OO + lane]      = v0;
        g_v[(size_t)p*OO + lane + 32] = v1;
        __syncwarp();
    }
}

// ---------------- KNN: 64 i x 128 j tiles, f32x2 FMA, double-buffered staging ----
// Dynamic smem: xsi (16KB) + xsj[2] (2 x 32KB) = 80KB. One barrier per chunk.
__global__ __launch_bounds__(256, 2) void k_knn(const float* __restrict__ x) {
    extern __shared__ __align__(16) float smem[];
    float* xsi = smem;              // [f][i], swizzle chunk4 = i4 ^ (f&15)
    float* xsj = smem + FF*64;      // two buffers of [f][j], chunk4 = j4 ^ (f&31)

    const int b  = blockIdx.y;
    const int i0 = blockIdx.x * 64;
    const float* xb  = x    + (size_t)b * NN * FF;
    const float* sqb = g_sq + b * NN;
    const int tid = threadIdx.x, lane = tid & 31, warp = tid >> 5;

    // stage the i-tile (transposed, swizzled)
    #pragma unroll
    for (int r = 0; r < 4; ++r) {
        int id = tid + 256*r;
        int f = id & 63, i4 = id >> 6;          // i4 in [0,16)
        float4 vv;
        vv.x = xb[(i0 + 4*i4 + 0)*FF + f];
        vv.y = xb[(i0 + 4*i4 + 1)*FF + f];
        vv.z = xb[(i0 + 4*i4 + 2)*FF + f];
        vv.w = xb[(i0 + 4*i4 + 3)*FF + f];
        *(float4*)&xsi[f*64 + 4*(i4 ^ (f & 15))] = vv;
    }

    // stage j-chunk 0 into buffer 0 (batched LDG for MLP, then STS)
    {
        const int f = tid & 63, j4 = tid >> 6;
        float4 vv[2];
        #pragma unroll
        for (int r = 0; r < 2; ++r) {
            int jj4 = j4 + 4*r;
            vv[r].x = xb[(4*jj4 + 0)*FF + f];
            vv[r].y = xb[(4*jj4 + 1)*FF + f];
            vv[r].z = xb[(4*jj4 + 2)*FF + f];
            vv[r].w = xb[(4*jj4 + 3)*FF + f];
        }
        // tid covers j4 0..3 (4 rounds of 256 needed) -> do remaining rounds
        #pragma unroll
        for (int r = 0; r < 2; ++r)
            *(float4*)&xsj[f*128 + 4*((j4 + 4*r) ^ (f & 31))] = vv[r];
        float4 ww[2];
        #pragma unroll
        for (int r = 2; r < 4; ++r) {
            int jj4 = j4 + 4*r;
            ww[r-2].x = xb[(4*jj4 + 0)*FF + f];
            ww[r-2].y = xb[(4*jj4 + 1)*FF + f];
            ww[r-2].z = xb[(4*jj4 + 2)*FF + f];
            ww[r-2].w = xb[(4*jj4 + 3)*FF + f];
        }
        #pragma unroll
        for (int r = 2; r < 4; ++r)
            *(float4*)&xsj[f*128 + 4*((j4 + 4*r) ^ (f & 31))] = ww[r-2];
        float4 uu[4];
        #pragma unroll
        for (int r = 4; r < 8; ++r) {
            int jj4 = j4 + 4*r;
            uu[r-4].x = xb[(4*jj4 + 0)*FF + f];
            uu[r-4].y = xb[(4*jj4 + 1)*FF + f];
            uu[r-4].z = xb[(4*jj4 + 2)*FF + f];
            uu[r-4].w = xb[(4*jj4 + 3)*FF + f];
        }
        #pragma unroll
        for (int r = 4; r < 8; ++r)
            *(float4*)&xsj[f*128 + 4*((j4 + 4*r) ^ (f & 31))] = uu[r-4];
    }

    float sqi[8];
    #pragma unroll
    for (int r = 0; r < 8; ++r) sqi[r] = sqb[i0 + 8*warp + r];

    // sorted top-20: lanes 0..19 hold ascending (val, idx); curmax = slot-19 value
    float bestv[8], curmax[8];
    int   besti[8];
    #pragma unroll
    for (int r = 0; r < 8; ++r) { bestv[r] = INFINITY; curmax[r] = INFINITY; besti[r] = 0; }

    __syncthreads();

    for (int jc = 0; jc < NCHUNK; ++jc) {
        const int j0 = jc * JCH;
        const float* cur = xsj + (jc & 1) * (FF*128);

        // stage NEXT chunk into the other buffer (overlaps with compute below)
        if (jc + 1 < NCHUNK) {
            float* nxt = xsj + ((jc + 1) & 1) * (FF*128);
            const int jn0 = j0 + JCH;
            const int f = tid & 63, j4 = tid >> 6;
            float4 vv[8];
            #pragma unroll
            for (int r = 0; r < 8; ++r) {
                int jj = jn0 + 4*(j4 + 4*r);
                vv[r].x = xb[(jj + 0)*FF + f];
                vv[r].y = xb[(jj + 1)*FF + f];
                vv[r].z = xb[(jj + 2)*FF + f];
                vv[r].w = xb[(jj + 3)*FF + f];
            }
            #pragma unroll
            for (int r = 0; r < 8; ++r)
                *(float4*)&nxt[f*128 + 4*((j4 + 4*r) ^ (f & 31))] = vv[r];
        }

        unsigned long long accP[4][4];
        #pragma unroll
        for (int m = 0; m < 4; ++m)
            #pragma unroll
            for (int q = 0; q < 4; ++q) accP[m][q] = 0ull;

        #pragma unroll 16
        for (int f = 0; f < FF; ++f) {
            ulonglong2 aA = *(const ulonglong2*)&xsi[f*64 + 4*((2*warp)     ^ (f & 15))];
            ulonglong2 aB = *(const ulonglong2*)&xsi[f*64 + 4*((2*warp + 1) ^ (f & 15))];
            float4 bv = *(const float4*)&cur[f*128 + 4*(lane ^ (f & 31))];
            unsigned long long b0 = dup2(bv.x), b1 = dup2(bv.y),
                               b2 = dup2(bv.z), b3 = dup2(bv.w);
            ffma2(accP[0][0], aA.x, b0); ffma2(accP[0][1], aA.x, b1);
            ffma2(accP[0][2], aA.x, b2); ffma2(accP[0][3], aA.x, b3);
            ffma2(accP[1][0], aA.y, b0); ffma2(accP[1][1], aA.y, b1);
            ffma2(accP[1][2], aA.y, b2); ffma2(accP[1][3], aA.y, b3);
            ffma2(accP[2][0], aB.x, b0); ffma2(accP[2][1], aB.x, b1);
            ffma2(accP[2][2], aB.x, b2); ffma2(accP[2][3], aB.x, b3);
            ffma2(accP[3][0], aB.y, b0); ffma2(accP[3][1], aB.y, b1);
            ffma2(accP[3][2], aB.y, b2); ffma2(accP[3][3], aB.y, b3);
        }

        float4 sq4 = *(const float4*)&sqb[j0 + 4*lane];
        const float sqj[4] = {sq4.x, sq4.y, sq4.z, sq4.w};

        #pragma unroll
        for (int m = 0; m < 4; ++m) {
            float dot[2][4];
            #pragma unroll
            for (int q = 0; q < 4; ++q) unpack2(accP[m][q], dot[0][q], dot[1][q]);

            #pragma unroll
            for (int h = 0; h < 2; ++h) {
                const int r  = 2*m + h;
                const int ig = i0 + 8*warp + r;
                const bool diag = (ig >> 7) == (j0 >> 7);
                float d[4];
                #pragma unroll
                for (int q = 0; q < 4; ++q)
                    d[q] = fmaf(-2.f, dot[h][q], sqi[r] + sqj[q]);
                if (diag) {
                    #pragma unroll
                    for (int q = 0; q < 4; ++q)
                        if (ig == j0 + 4*lane + q) d[q] = INFINITY;
                }
                float dmin = fminf(fminf(d[0], d[1]), fminf(d[2], d[3]));
                if (__ballot_sync(FULLM, dmin < curmax[r])) {
                    #pragma unroll
                    for (int q = 0; q < 4; ++q) {
                        float v = d[q];
                        unsigned mmask = __ballot_sync(FULLM, v < curmax[r]);
                        while (mmask) {
                            int src  = __ffs(mmask) - 1;
                            float cv = __shfl_sync(FULLM, v, src);
                            int   cj = j0 + 4*src + q;
                            float upv = __shfl_up_sync(FULLM, bestv[r], 1);
                            int   upi = __shfl_up_sync(FULLM, besti[r], 1);
                            float p18 = __shfl_sync(FULLM, bestv[r], 18);
                            bool shift = (lane < KK) && (bestv[r] > cv);
                            unsigned pm = __ballot_sync(FULLM, shift);
                            int first = __ffs(pm) - 1;
                            if (shift) {
                                bestv[r] = (lane == first) ? cv : upv;
                                besti[r] = (lane == first) ? cj : upi;
                            }
                            curmax[r] = fmaxf(p18, cv);
                            if (lane == src) v = INFINITY;
                            mmask = __ballot_sync(FULLM, v < curmax[r]);
                        }
                    }
                }
            }
        }
        __syncthreads();
    }

    #pragma unroll
    for (int r = 0; r < 8; ++r)
        if (lane < KK)
            g_idx[(size_t)(b*NN + i0 + 8*warp + r)*KK + lane] = besti[r];
}

// ---------------- fuse: h = u_n + v_j, max/min, channel sums; last block -> BN ---
__global__ __launch_bounds__(256) void k_fuse(const float* __restrict__ gamma,
                                              const float* __restrict__ beta) {
    const int tid = threadIdx.x, lane = tid & 31, warp = tid >> 5;
    const int p0 = blockIdx.x * 64 + warp * 8;
    float s0 = 0.f, s1 = 0.f, q0 = 0.f, q1 = 0.f;

    for (int pp = 0; pp < 8; ++pp) {
        const int p = p0 + pp;
        const int vbase = (p >> 12) << 18;   // (p/4096)*4096*64
        int myj = 0;
        if (lane < KK) myj = g_idx[(size_t)p*KK + lane];
        float u0 = g_u[(size_t)p*OO + lane];
        float u1 = g_u[(size_t)p*OO + lane + 32];
        float mx0 = -INFINITY, mx1 = -INFINITY, mn0 = INFINITY, mn1 = INFINITY;
        #pragma unroll
        for (int k = 0; k < KK; ++k) {
            int j = __shfl_sync(FULLM, myj, k);
            const float* vp = g_v + vbase + j*OO;
            float v0 = vp[lane], v1 = vp[lane + 32];
            float h0 = u0 + v0, h1 = u1 + v1;
            mx0 = fmaxf(mx0, h0); mn0 = fminf(mn0, h0);
            mx1 = fmaxf(mx1, h1); mn1 = fminf(mn1, h1);
            s0 += h0; q0 = fmaf(h0, h0, q0);
            s1 += h1; q1 = fmaf(h1, h1, q1);
        }
        g_hmax[(size_t)p*OO + lane]      = mx0;
        g_hmax[(size_t)p*OO + lane + 32] = mx1;
        g_hmin[(size_t)p*OO + lane]      = mn0;
        g_hmin[(size_t)p*OO + lane + 32] = mn1;
    }

    __shared__ float sb[8][OO], qb[8][OO];
    sb[warp][lane] = s0; sb[warp][lane + 32] = s1;
    qb[warp][lane] = q0; qb[warp][lane + 32] = q1;
    __syncthreads();
    if (tid < OO) {
        float a = 0.f, c = 0.f;
        #pragma unroll
        for (int w = 0; w < 8; ++w) { a += sb[w][tid]; c += qb[w][tid]; }
        atomicAdd(&g_sum[tid], (double)a);
        atomicAdd(&g_ssq[tid], (double)c);
    }
    __syncthreads();

    __shared__ int amLast;
    if (tid == 0) {
        __threadfence();
        amLast = (atomicAdd(&g_ctr, 1) == (int)gridDim.x - 1);
    }
    __syncthreads();
    if (amLast) {
        __threadfence();
        if (tid < OO) {
            const double cnt = (double)NPTS * (double)KK;
            double m   = g_sum[tid] / cnt;
            double var = g_ssq[tid] / cnt - m * m;
            float a = gamma[tid] * rsqrtf((float)var + 1e-5f);
            g_scale[tid] = a;
            g_shift[tid] = beta[tid] - (float)m * a;
        }
    }
}

// ---------------- apply BN + ReLU to the pooled extrema ----------------
__global__ __launch_bounds__(256) void k_final(float* __restrict__ out) {
    int t = blockIdx.x * 256 + threadIdx.x;          // 4 floats per thread
    float4 mx = ((const float4*)g_hmax)[t];
    float4 mn = ((const float4*)g_hmin)[t];
    int o = (t * 4) & 63;
    float a0 = g_scale[o+0], a1 = g_scale[o+1], a2 = g_scale[o+2], a3 = g_scale[o+3];
    float4 r;
    r.x = fmaxf(fmaf(a0, (a0 >= 0.f) ? mx.x : mn.x, g_shift[o+0]), 0.f);
    r.y = fmaxf(fmaf(a1, (a1 >= 0.f) ? mx.y : mn.y, g_shift[o+1]), 0.f);
    r.z = fmaxf(fmaf(a2, (a2 >= 0.f) ? mx.z : mn.z, g_shift[o+2]), 0.f);
    r.w = fmaxf(fmaf(a3, (a3 >= 0.f) ? mx.w : mn.w, g_shift[o+3]), 0.f);
    ((float4*)out)[t] = r;
}

extern "C" void kernel_launch(void* const* d_in, const int* in_sizes, int n_in,
                              void* d_out, int out_size) {
    const float* x     = (const float*)d_in[0];
    const float* W     = (const float*)d_in[1];
    // d_in[2] (conv bias b) cancels exactly under BatchNorm: unused.
    const float* gamma = (const float*)d_in[3];
    const float* beta  = (const float*)d_in[4];
    float* out = (float*)d_out;

    const int knn_smem = (FF*64 + 2*FF*128) * sizeof(float);   // 80 KB
    cudaFuncSetAttribute(k_knn, cudaFuncAttributeMaxDynamicSharedMemorySize, knn_smem);

    k_uv   <<<NPTS/64, 256>>>(x, W);
    k_knn  <<<dim3(NN/64, BB), 256, knn_smem>>>(x);
    k_fuse <<<NPTS/64, 256>>>(gamma, beta);
    k_final<<<NPTS*OO/1024, 256>>>(out);
}